// round 3
// baseline (speedup 1.0000x reference)
#include <cuda_runtime.h>
#include <cuda_bf16.h>
#include <mma.h>
#include <type_traits>
#include <cstdint>

using namespace nvcuda;

// Problem constants
#define DMODEL 1024
#define NHEADS 16
#define DKHEAD 64
#define DFF    4096
#define BATCH  2
#define SEQ    2048
#define MROWS  (BATCH*SEQ)   // 4096

// ---------------- scratch (device globals; allocation-free rule) ----------------
__device__ float g_Q[(size_t)MROWS*DMODEL];
__device__ float g_Kb[(size_t)MROWS*DMODEL];
__device__ float g_V[(size_t)MROWS*DMODEL];
__device__ float g_scores[(size_t)BATCH*NHEADS*SEQ*SEQ];   // 512 MB
__device__ float g_attn[(size_t)MROWS*DMODEL];
__device__ float g_attnout[(size_t)MROWS*DMODEL];
__device__ float g_h[(size_t)MROWS*DMODEL];
__device__ float g_ffmid[(size_t)MROWS*DFF];
__device__ float g_ffout[(size_t)MROWS*DMODEL];

// ---------------- TF32 wmma GEMM ----------------
// C = A(MxK, row-major, lda) * op(B) ; op(B)=B (KxN row-major) or B^T (B is NxK row-major)
// Tiles: 128x128x32, 8 warps in 4x2 grid, warp tile 32x64 (2x4 wmma 16x16x8 frags).
// Batched via blockIdx.z with composite (outer/inner) strides: off = (z/zdiv)*so + (z%zdiv)*si.

constexpr int BM = 128, BN = 128, BK = 32;

template<class Frag>
__device__ __forceinline__ void frag_to_tf32(Frag& f) {
#pragma unroll
    for (int t = 0; t < f.num_elements; t++) f.x[t] = wmma::__float_to_tf32(f.x[t]);
}

template<bool TRANS_B>
__global__ void __launch_bounds__(256, 1) gemm_kernel(
    const float* __restrict__ A, const float* __restrict__ B, float* __restrict__ C,
    int M, int N, int K, int lda, int ldb, int ldc,
    long long sAo, long long sAi, long long sBo, long long sBi,
    long long sCo, long long sCi, int zdiv)
{
    __shared__ float As[BM][BK + 4];          // 128 x 36
    __shared__ float Bs[BM * (BK + 4)];       // max(128*36 [NT], 32*132 [NN])

    const int bz = blockIdx.z;
    const int zo = bz / zdiv, zi = bz % zdiv;
    A += (long long)zo * sAo + (long long)zi * sAi;
    B += (long long)zo * sBo + (long long)zi * sBi;
    C += (long long)zo * sCo + (long long)zi * sCi;

    const int m0 = blockIdx.y * BM;
    const int n0 = blockIdx.x * BN;
    const int tid = threadIdx.x;
    const int warp = tid >> 5;
    const int wm = warp >> 1;     // 0..3
    const int wn = warp & 1;      // 0..1

    wmma::fragment<wmma::matrix_a, 16, 16, 8, wmma::precision::tf32, wmma::row_major> af[2];
    using BL = typename std::conditional<TRANS_B, wmma::col_major, wmma::row_major>::type;
    wmma::fragment<wmma::matrix_b, 16, 16, 8, wmma::precision::tf32, BL> bf[4];
    wmma::fragment<wmma::accumulator, 16, 16, 8, float> cf[2][4];

#pragma unroll
    for (int i = 0; i < 2; i++)
#pragma unroll
        for (int j = 0; j < 4; j++) wmma::fill_fragment(cf[i][j], 0.0f);

    const float4 zero4 = make_float4(0.f, 0.f, 0.f, 0.f);

    for (int kk = 0; kk < K; kk += BK) {
        // load A tile: 128x32 (1024 float4, 4 per thread)
#pragma unroll
        for (int i = 0; i < 4; i++) {
            int idx = tid + i * 256;
            int r = idx >> 3, c4 = (idx & 7) * 4;
            *(float4*)&As[r][c4] =
                *(const float4*)&A[(size_t)(m0 + r) * lda + kk + c4];
        }
        if (TRANS_B) {
            // B tile: rows = n (128), cols = k (32)
#pragma unroll
            for (int i = 0; i < 4; i++) {
                int idx = tid + i * 256;
                int r = idx >> 3, c4 = (idx & 7) * 4;
                float4 v = (n0 + r < N)
                    ? *(const float4*)&B[(size_t)(n0 + r) * ldb + kk + c4]
                    : zero4;
                *(float4*)&Bs[r * (BK + 4) + c4] = v;
            }
        } else {
            // B tile: rows = k (32), cols = n (128)
#pragma unroll
            for (int i = 0; i < 4; i++) {
                int idx = tid + i * 256;
                int r = idx >> 5, c4 = (idx & 31) * 4;
                int col = n0 + c4;
                float4 v = (col < N)
                    ? *(const float4*)&B[(size_t)(kk + r) * ldb + col]
                    : zero4;
                *(float4*)&Bs[r * (BN + 4) + c4] = v;
            }
        }
        __syncthreads();

#pragma unroll
        for (int k4 = 0; k4 < 4; k4++) {
            const int kc = k4 * 8;
#pragma unroll
            for (int i = 0; i < 2; i++) {
                wmma::load_matrix_sync(af[i], &As[wm * 32 + i * 16][kc], BK + 4);
                frag_to_tf32(af[i]);
            }
#pragma unroll
            for (int j = 0; j < 4; j++) {
                if (TRANS_B)
                    wmma::load_matrix_sync(bf[j], &Bs[(wn * 64 + j * 16) * (BK + 4) + kc], BK + 4);
                else
                    wmma::load_matrix_sync(bf[j], &Bs[kc * (BN + 4) + wn * 64 + j * 16], BN + 4);
                frag_to_tf32(bf[j]);
            }
#pragma unroll
            for (int i = 0; i < 2; i++)
#pragma unroll
                for (int j = 0; j < 4; j++)
                    wmma::mma_sync(cf[i][j], af[i], bf[j], cf[i][j]);
        }
        __syncthreads();
    }

#pragma unroll
    for (int i = 0; i < 2; i++)
#pragma unroll
        for (int j = 0; j < 4; j++) {
            int cn = n0 + wn * 64 + j * 16;
            if (cn < N)
                wmma::store_matrix_sync(&C[(size_t)(m0 + wm * 32 + i * 16) * ldc + cn],
                                        cf[i][j], ldc, wmma::mem_row_major);
        }
}

// ---------------- elementwise / reductions ----------------
__device__ __forceinline__ float warpMax(float v) {
#pragma unroll
    for (int o = 16; o; o >>= 1) v = fmaxf(v, __shfl_xor_sync(0xffffffffu, v, o));
    return v;
}
__device__ __forceinline__ float warpSum(float v) {
#pragma unroll
    for (int o = 16; o; o >>= 1) v += __shfl_xor_sync(0xffffffffu, v, o);
    return v;
}

__device__ float blockMax256(float v) {
    __shared__ float s[8];
    v = warpMax(v);
    if ((threadIdx.x & 31) == 0) s[threadIdx.x >> 5] = v;
    __syncthreads();
    if (threadIdx.x < 32) {
        float w = (threadIdx.x < 8) ? s[threadIdx.x] : -1e30f;
        w = warpMax(w);
        if (threadIdx.x == 0) s[0] = w;
    }
    __syncthreads();
    float r = s[0];
    __syncthreads();
    return r;
}

__device__ float blockSum256(float v) {
    __shared__ float s[8];
    v = warpSum(v);
    if ((threadIdx.x & 31) == 0) s[threadIdx.x >> 5] = v;
    __syncthreads();
    if (threadIdx.x < 32) {
        float w = (threadIdx.x < 8) ? s[threadIdx.x] : 0.f;
        w = warpSum(w);
        if (threadIdx.x == 0) s[0] = w;
    }
    __syncthreads();
    float r = s[0];
    __syncthreads();
    return r;
}

__global__ void bias_act_kernel(float* __restrict__ y, const float* __restrict__ bias,
                                int nmask, long long total, int relu) {
    long long i = (long long)blockIdx.x * blockDim.x + threadIdx.x;
    long long stride = (long long)gridDim.x * blockDim.x;
    for (; i < total; i += stride) {
        float v = y[i] + bias[(int)(i & nmask)];
        y[i] = relu ? fmaxf(v, 0.f) : v;
    }
}

// rows = B*H*S, each block does one row of SEQ; scale 1/sqrt(64), mask, softmax in place
__global__ void softmax_kernel(float* __restrict__ sc, const int* __restrict__ mask) {
    long long row = blockIdx.x;
    int b = (int)(row / ((long long)NHEADS * SEQ));
    float* p = sc + row * (long long)SEQ;
    const int* mrow = mask + (size_t)b * SEQ;
    const int t = threadIdx.x;

    float vals[8];
    float mx = -1e30f;
#pragma unroll
    for (int i = 0; i < 8; i++) {
        int c = t + i * 256;
        float v = p[c] * 0.125f;
        v = (mrow[c] == 0) ? -1e30f : v;
        vals[i] = v;
        mx = fmaxf(mx, v);
    }
    mx = blockMax256(mx);
    float sum = 0.f;
#pragma unroll
    for (int i = 0; i < 8; i++) { vals[i] = __expf(vals[i] - mx); sum += vals[i]; }
    sum = blockSum256(sum);
    float inv = 1.f / sum;
#pragma unroll
    for (int i = 0; i < 8; i++) p[t + i * 256] = vals[i] * inv;
}

// out = LayerNorm(a + b + bias) * gamma + beta, rows of DMODEL=1024, 256 threads
__global__ void ln_kernel(const float* __restrict__ a, const float* __restrict__ bsrc,
                          const float* __restrict__ bias,
                          const float* __restrict__ gamma, const float* __restrict__ beta,
                          float* __restrict__ out) {
    int row = blockIdx.x;
    const float* ar = a + (size_t)row * DMODEL;
    const float* br = bsrc + (size_t)row * DMODEL;
    float v[4];
    float s = 0.f;
#pragma unroll
    for (int i = 0; i < 4; i++) {
        int c = threadIdx.x + i * 256;
        v[i] = ar[c] + br[c] + bias[c];
        s += v[i];
    }
    s = blockSum256(s);
    float mu = s * (1.0f / DMODEL);
    float q = 0.f;
#pragma unroll
    for (int i = 0; i < 4; i++) { float d = v[i] - mu; q += d * d; }
    q = blockSum256(q);
    float rstd = rsqrtf(q * (1.0f / DMODEL) + 1e-5f);
#pragma unroll
    for (int i = 0; i < 4; i++) {
        int c = threadIdx.x + i * 256;
        out[(size_t)row * DMODEL + c] = (v[i] - mu) * rstd * gamma[c] + beta[c];
    }
}

// ---------------- launch ----------------
extern "C" void kernel_launch(void* const* d_in, const int* in_sizes, int n_in,
                              void* d_out, int out_size) {
    const float* x    = (const float*)d_in[0];
    const int*   mask = (const int*)  d_in[1];
    const float* Wq   = (const float*)d_in[2];
    const float* bq   = (const float*)d_in[3];
    const float* Wk   = (const float*)d_in[4];
    const float* bk   = (const float*)d_in[5];
    const float* Wv   = (const float*)d_in[6];
    const float* bv   = (const float*)d_in[7];
    const float* Wo   = (const float*)d_in[8];
    const float* bo   = (const float*)d_in[9];
    const float* W1   = (const float*)d_in[10];
    const float* b1   = (const float*)d_in[11];
    const float* W2   = (const float*)d_in[12];
    const float* b2   = (const float*)d_in[13];
    const float* g1   = (const float*)d_in[14];
    const float* be1  = (const float*)d_in[15];
    const float* g2   = (const float*)d_in[16];
    const float* be2  = (const float*)d_in[17];
    float* out = (float*)d_out;

    float *Q, *Kb, *V, *Sc, *At, *Ao, *H, *F1, *F2;
    cudaGetSymbolAddress((void**)&Q,  g_Q);
    cudaGetSymbolAddress((void**)&Kb, g_Kb);
    cudaGetSymbolAddress((void**)&V,  g_V);
    cudaGetSymbolAddress((void**)&Sc, g_scores);
    cudaGetSymbolAddress((void**)&At, g_attn);
    cudaGetSymbolAddress((void**)&Ao, g_attnout);
    cudaGetSymbolAddress((void**)&H,  g_h);
    cudaGetSymbolAddress((void**)&F1, g_ffmid);
    cudaGetSymbolAddress((void**)&F2, g_ffout);

    const dim3 thr(256);
    const long long Z = 0;

    // QKV projections: [4096,1024] = x[4096,1024] @ W[1024,1024]
    dim3 gproj(DMODEL / BN, MROWS / BM, 1);
    gemm_kernel<false><<<gproj, thr>>>(x, Wq, Q, MROWS, DMODEL, DMODEL, DMODEL, DMODEL, DMODEL, Z, Z, Z, Z, Z, Z, 1);
    gemm_kernel<false><<<gproj, thr>>>(x, Wk, Kb, MROWS, DMODEL, DMODEL, DMODEL, DMODEL, DMODEL, Z, Z, Z, Z, Z, Z, 1);
    gemm_kernel<false><<<gproj, thr>>>(x, Wv, V, MROWS, DMODEL, DMODEL, DMODEL, DMODEL, DMODEL, Z, Z, Z, Z, Z, Z, 1);

    long long totalD = (long long)MROWS * DMODEL;
    bias_act_kernel<<<2048, thr>>>(Q,  bq, DMODEL - 1, totalD, 0);
    bias_act_kernel<<<2048, thr>>>(Kb, bk, DMODEL - 1, totalD, 0);
    bias_act_kernel<<<2048, thr>>>(V,  bv, DMODEL - 1, totalD, 0);

    // scores[b,h] = Q_bh [2048,64] @ K_bh^T  (NT, batched over 32)
    {
        long long sQo = (long long)SEQ * DMODEL, sQi = DKHEAD;        // b, h strides
        long long sSo = (long long)NHEADS * SEQ * SEQ, sSi = (long long)SEQ * SEQ;
        dim3 g(SEQ / BN, SEQ / BM, BATCH * NHEADS);
        gemm_kernel<true><<<g, thr>>>(Q, Kb, Sc, SEQ, SEQ, DKHEAD,
                                      DMODEL, DMODEL, SEQ,
                                      sQo, sQi, sQo, sQi, sSo, sSi, NHEADS);
    }

    // softmax with mask + 1/sqrt(dk)
    softmax_kernel<<<BATCH * NHEADS * SEQ, thr>>>(Sc, mask);

    // attn[b,h] = P_bh [2048,2048] @ V_bh [2048,64]  (NN, batched over 32)
    {
        long long sPo = (long long)NHEADS * SEQ * SEQ, sPi = (long long)SEQ * SEQ;
        long long sVo = (long long)SEQ * DMODEL, sVi = DKHEAD;
        dim3 g(1, SEQ / BM, BATCH * NHEADS);
        gemm_kernel<false><<<g, thr>>>(Sc, V, At, SEQ, DKHEAD, SEQ,
                                       SEQ, DMODEL, DMODEL,
                                       sPo, sPi, sVo, sVi, sVo, sVi, NHEADS);
    }

    // attn_out = attn @ Wo  (bias bo folded into LN1)
    gemm_kernel<false><<<gproj, thr>>>(At, Wo, Ao, MROWS, DMODEL, DMODEL, DMODEL, DMODEL, DMODEL, Z, Z, Z, Z, Z, Z, 1);

    // h = LN(x + attn_out + bo)
    ln_kernel<<<MROWS, thr>>>(x, Ao, bo, g1, be1, H);

    // ff_mid = relu(h @ W1 + b1)
    {
        dim3 g(DFF / BN, MROWS / BM, 1);
        gemm_kernel<false><<<g, thr>>>(H, W1, F1, MROWS, DFF, DMODEL, DMODEL, DFF, DFF, Z, Z, Z, Z, Z, Z, 1);
        bias_act_kernel<<<4096, thr>>>(F1, b1, DFF - 1, (long long)MROWS * DFF, 1);
    }

    // ff_out = ff_mid @ W2  (bias b2 folded into LN2)
    gemm_kernel<false><<<gproj, thr>>>(F1, W2, F2, MROWS, DMODEL, DFF, DFF, DMODEL, DMODEL, Z, Z, Z, Z, Z, Z, 1);

    // out = LN(h + ff_out + b2)
    ln_kernel<<<MROWS, thr>>>(H, F2, b2, g2, be2, out);
}

// round 5
// speedup vs baseline: 1.0153x; 1.0153x over previous
#include <cuda_runtime.h>
#include <cuda_bf16.h>
#include <mma.h>
#include <cstdint>

using namespace nvcuda;

#define DMODEL 1024
#define NHEADS 16
#define DKHEAD 64
#define DFF    4096
#define BATCH  2
#define SEQ    2048
#define MROWS  (BATCH*SEQ)   // 4096

// ---------------- scratch ----------------
__device__ float g_Q[(size_t)MROWS*DMODEL];
__device__ float g_Kb[(size_t)MROWS*DMODEL];
__device__ float g_V[(size_t)MROWS*DMODEL];
__device__ float g_attn[(size_t)MROWS*DMODEL];
__device__ float g_attnout[(size_t)MROWS*DMODEL];
__device__ float g_h[(size_t)MROWS*DMODEL];
__device__ float g_ffmid[(size_t)MROWS*DFF];
__device__ float g_ffout[(size_t)MROWS*DMODEL];

// ---------------- helpers ----------------
template<class Frag>
__device__ __forceinline__ void frag_to_tf32(Frag& f) {
#pragma unroll
    for (int t = 0; t < f.num_elements; t++) f.x[t] = wmma::__float_to_tf32(f.x[t]);
}

__device__ __forceinline__ void cp16(float* s, const float* g) {
    uint32_t sa = (uint32_t)__cvta_generic_to_shared(s);
    asm volatile("cp.async.cg.shared.global [%0], [%1], 16;" :: "r"(sa), "l"(g));
}
__device__ __forceinline__ void cp_commit() { asm volatile("cp.async.commit_group;"); }

__device__ __forceinline__ float warpMax(float v) {
#pragma unroll
    for (int o = 16; o; o >>= 1) v = fmaxf(v, __shfl_xor_sync(0xffffffffu, v, o));
    return v;
}
__device__ __forceinline__ float warpSum(float v) {
#pragma unroll
    for (int o = 16; o; o >>= 1) v += __shfl_xor_sync(0xffffffffu, v, o);
    return v;
}
__device__ float blockSum256(float v) {
    __shared__ float s[8];
    v = warpSum(v);
    if ((threadIdx.x & 31) == 0) s[threadIdx.x >> 5] = v;
    __syncthreads();
    if (threadIdx.x < 32) {
        float w = (threadIdx.x < 8) ? s[threadIdx.x] : 0.f;
        w = warpSum(w);
        if (threadIdx.x == 0) s[0] = w;
    }
    __syncthreads();
    float r = s[0];
    __syncthreads();
    return r;
}

// ---------------- cp.async double-buffered TF32 NN GEMM ----------------
// C[M,N] = A[M,K] @ B[K,N], all row-major; M%128==0, N%128==0, K%32==0.
constexpr int BM = 128, BN = 128, BK = 32;
constexpr int AS_STRIDE = BK + 4;            // 36
constexpr int BS_STRIDE = BN + 4;            // 132
constexpr int AS_STAGE = BM * AS_STRIDE;     // 4608
constexpr int BS_STAGE = BK * BS_STRIDE;     // 4224
constexpr int GEMM_SMEM_BYTES = (2 * AS_STAGE + 2 * BS_STAGE) * 4;  // 70656

__global__ void __launch_bounds__(256) gemm_nn(
    const float* __restrict__ A, const float* __restrict__ B, float* __restrict__ C,
    int M, int N, int K, int lda, int ldb, int ldc)
{
    extern __shared__ float sm[];
    float* As = sm;                      // 2 stages of [128][36]
    float* Bs = sm + 2 * AS_STAGE;       // 2 stages of [32][132]

    const int m0 = blockIdx.y * BM;
    const int n0 = blockIdx.x * BN;
    const int tid = threadIdx.x;
    const int warp = tid >> 5;
    const int wm = warp >> 1;   // 0..3
    const int wn = warp & 1;    // 0..1

    wmma::fragment<wmma::matrix_a, 16, 16, 8, wmma::precision::tf32, wmma::row_major> af[2];
    wmma::fragment<wmma::matrix_b, 16, 16, 8, wmma::precision::tf32, wmma::row_major> bf[4];
    wmma::fragment<wmma::accumulator, 16, 16, 8, float> cf[2][4];
#pragma unroll
    for (int i = 0; i < 2; i++)
#pragma unroll
        for (int j = 0; j < 4; j++) wmma::fill_fragment(cf[i][j], 0.0f);

    auto loadA = [&](int st, int kk) {
#pragma unroll
        for (int i = 0; i < 4; i++) {
            int idx = tid + i * 256;
            int r = idx >> 3, c4 = (idx & 7) * 4;
            cp16(&As[st * AS_STAGE + r * AS_STRIDE + c4],
                 &A[(size_t)(m0 + r) * lda + kk + c4]);
        }
    };
    auto loadB = [&](int st, int kk) {
#pragma unroll
        for (int i = 0; i < 4; i++) {
            int idx = tid + i * 256;
            int r = idx >> 5, c4 = (idx & 31) * 4;
            cp16(&Bs[st * BS_STAGE + r * BS_STRIDE + c4],
                 &B[(size_t)(kk + r) * ldb + n0 + c4]);
        }
    };

    loadA(0, 0); loadB(0, 0); cp_commit();

    const int nk = K / BK;
    for (int t = 0; t < nk; t++) {
        if (t + 1 < nk) {
            loadA((t + 1) & 1, (t + 1) * BK);
            loadB((t + 1) & 1, (t + 1) * BK);
            cp_commit();
            asm volatile("cp.async.wait_group 1;");
        } else {
            asm volatile("cp.async.wait_group 0;");
        }
        __syncthreads();

        const int st = t & 1;
        const float* Ab = &As[st * AS_STAGE];
        const float* Bb = &Bs[st * BS_STAGE];
#pragma unroll
        for (int k4 = 0; k4 < 4; k4++) {
            const int kc = k4 * 8;
#pragma unroll
            for (int i = 0; i < 2; i++) {
                wmma::load_matrix_sync(af[i], &Ab[(wm * 32 + i * 16) * AS_STRIDE + kc], AS_STRIDE);
                frag_to_tf32(af[i]);
            }
#pragma unroll
            for (int j = 0; j < 4; j++) {
                wmma::load_matrix_sync(bf[j], &Bb[kc * BS_STRIDE + wn * 64 + j * 16], BS_STRIDE);
                frag_to_tf32(bf[j]);
            }
#pragma unroll
            for (int i = 0; i < 2; i++)
#pragma unroll
                for (int j = 0; j < 4; j++)
                    wmma::mma_sync(cf[i][j], af[i], bf[j], cf[i][j]);
        }
        __syncthreads();
    }

#pragma unroll
    for (int i = 0; i < 2; i++)
#pragma unroll
        for (int j = 0; j < 4; j++)
            wmma::store_matrix_sync(&C[(size_t)(m0 + wm * 32 + i * 16) * ldc + n0 + wn * 64 + j * 16],
                                    cf[i][j], ldc, wmma::mem_row_major);
}

// ---------------- flash attention (TF32 wmma, online softmax) ----------------
// grid (SEQ/128, BATCH*NHEADS), 256 threads. Q/K/V are [MROWS, DMODEL] projections
// WITHOUT bias; biases folded in here. Output written to g_attn [MROWS, DMODEL].
constexpr int FBM = 128, FBN = 64;
constexpr int FST = DKHEAD + 4;  // 68
// smem floats: Qs 128*68, Ks 64*68, Vs 64*68, Ss 128*68, Os 128*68, m/l/a 384,
//              bk 64, bv 64, mask 64(int)
constexpr int FLASH_SMEM_BYTES = (FBM*FST + FBN*FST + FBN*FST + FBM*FST + FBM*FST
                                  + 3*FBM + 64 + 64 + 64) * 4;

__global__ void __launch_bounds__(256) flash_kernel(
    const float* __restrict__ Q, const float* __restrict__ K, const float* __restrict__ V,
    const float* __restrict__ bq, const float* __restrict__ bk, const float* __restrict__ bv,
    const int* __restrict__ mask, float* __restrict__ Oout)
{
    extern __shared__ float fsm[];
    float* Qs = fsm;
    float* Ks = Qs + FBM * FST;
    float* Vs = Ks + FBN * FST;
    float* Ss = Vs + FBN * FST;
    float* Os = Ss + FBM * FST;
    float* mS = Os + FBM * FST;
    float* lS = mS + FBM;
    float* aS = lS + FBM;
    float* bkS = aS + FBM;
    float* bvS = bkS + 64;
    int*   mkS = (int*)(bvS + 64);

    const int mt = blockIdx.x;
    const int bh = blockIdx.y;
    const int b = bh >> 4, h = bh & 15;
    const int tid = threadIdx.x, warp = tid >> 5, lane = tid & 31;

    const float* Qg = Q + ((size_t)(b * SEQ + mt * FBM)) * DMODEL + h * DKHEAD;
    const float* Kg = K + ((size_t)(b * SEQ)) * DMODEL + h * DKHEAD;
    const float* Vg = V + ((size_t)(b * SEQ)) * DMODEL + h * DKHEAD;

    if (tid < 64) { bkS[tid] = bk[h * 64 + tid]; bvS[tid] = bv[h * 64 + tid]; }
    if (tid < FBM) { mS[tid] = -1e30f; lS[tid] = 0.f; }
    __syncthreads();

    // Q tile 128x64 with bias: 2048 float4, 8 per thread
#pragma unroll
    for (int i = 0; i < 8; i++) {
        int idx = tid + i * 256;
        int r = idx >> 4, c4 = (idx & 15) * 4;
        float4 v = *(const float4*)&Qg[(size_t)r * DMODEL + c4];
        v.x += bq[h * 64 + c4 + 0]; v.y += bq[h * 64 + c4 + 1];
        v.z += bq[h * 64 + c4 + 2]; v.w += bq[h * 64 + c4 + 3];
        *(float4*)&Qs[r * FST + c4] = v;
    }
#pragma unroll
    for (int i = 0; i < 32; i++) {
        int idx = tid + i * 256;
        Os[(idx >> 6) * FST + (idx & 63)] = 0.f;
    }
    __syncthreads();

    const int wm = warp >> 1;   // 0..3
    const int wn = warp & 1;    // 0..1

    for (int j0 = 0; j0 < SEQ; j0 += FBN) {
        // K, V tiles 64x64 each (1024 float4 each, 4 per thread each)
#pragma unroll
        for (int i = 0; i < 4; i++) {
            int idx = tid + i * 256;
            int r = idx >> 4, c4 = (idx & 15) * 4;
            float4 kv = *(const float4*)&Kg[(size_t)(j0 + r) * DMODEL + c4];
            kv.x += bkS[c4 + 0]; kv.y += bkS[c4 + 1]; kv.z += bkS[c4 + 2]; kv.w += bkS[c4 + 3];
            *(float4*)&Ks[r * FST + c4] = kv;
            float4 vv = *(const float4*)&Vg[(size_t)(j0 + r) * DMODEL + c4];
            vv.x += bvS[c4 + 0]; vv.y += bvS[c4 + 1]; vv.z += bvS[c4 + 2]; vv.w += bvS[c4 + 3];
            *(float4*)&Vs[r * FST + c4] = vv;
        }
        if (tid < 64) mkS[tid] = mask[(size_t)b * SEQ + j0 + tid];
        __syncthreads();

        // S = Q @ K^T : warp tile 32x32 at (wm*32, wn*32)
        {
            wmma::fragment<wmma::matrix_a, 16, 16, 8, wmma::precision::tf32, wmma::row_major> af[2];
            wmma::fragment<wmma::matrix_b, 16, 16, 8, wmma::precision::tf32, wmma::col_major> bf[2];
            wmma::fragment<wmma::accumulator, 16, 16, 8, float> sf[2][2];
#pragma unroll
            for (int i = 0; i < 2; i++)
#pragma unroll
                for (int j = 0; j < 2; j++) wmma::fill_fragment(sf[i][j], 0.0f);
#pragma unroll
            for (int kc = 0; kc < DKHEAD; kc += 8) {
#pragma unroll
                for (int i = 0; i < 2; i++) {
                    wmma::load_matrix_sync(af[i], &Qs[(wm * 32 + i * 16) * FST + kc], FST);
                    frag_to_tf32(af[i]);
                }
#pragma unroll
                for (int j = 0; j < 2; j++) {
                    wmma::load_matrix_sync(bf[j], &Ks[(wn * 32 + j * 16) * FST + kc], FST);
                    frag_to_tf32(bf[j]);
                }
#pragma unroll
                for (int i = 0; i < 2; i++)
#pragma unroll
                    for (int j = 0; j < 2; j++)
                        wmma::mma_sync(sf[i][j], af[i], bf[j], sf[i][j]);
            }
#pragma unroll
            for (int i = 0; i < 2; i++)
#pragma unroll
                for (int j = 0; j < 2; j++)
                    wmma::store_matrix_sync(&Ss[(wm * 32 + i * 16) * FST + wn * 32 + j * 16],
                                            sf[i][j], FST, wmma::mem_row_major);
        }
        __syncthreads();

        // online softmax: warp owns rows warp*16..+15
        {
            const int mk0 = mkS[lane], mk1 = mkS[lane + 32];
#pragma unroll
            for (int rr = 0; rr < 16; rr++) {
                int r = warp * 16 + rr;
                float v0 = Ss[r * FST + lane] * 0.125f;
                float v1 = Ss[r * FST + 32 + lane] * 0.125f;
                if (mk0 == 0) v0 = -1e30f;
                if (mk1 == 0) v1 = -1e30f;
                float rmx = warpMax(fmaxf(v0, v1));
                float mold = mS[r];
                float mnew = fmaxf(mold, rmx);
                float p0 = __expf(v0 - mnew);
                float p1 = __expf(v1 - mnew);
                float rs = warpSum(p0 + p1);
                if (lane == 0) {
                    float al = __expf(mold - mnew);
                    aS[r] = al;
                    lS[r] = lS[r] * al + rs;
                    mS[r] = mnew;
                }
                Ss[r * FST + lane] = p0;
                Ss[r * FST + 32 + lane] = p1;
            }
        }
        __syncthreads();

        // U = P @ V
        {
            wmma::fragment<wmma::matrix_a, 16, 16, 8, wmma::precision::tf32, wmma::row_major> af[2];
            wmma::fragment<wmma::matrix_b, 16, 16, 8, wmma::precision::tf32, wmma::row_major> bf[2];
            wmma::fragment<wmma::accumulator, 16, 16, 8, float> uf[2][2];
#pragma unroll
            for (int i = 0; i < 2; i++)
#pragma unroll
                for (int j = 0; j < 2; j++) wmma::fill_fragment(uf[i][j], 0.0f);
#pragma unroll
            for (int kc = 0; kc < FBN; kc += 8) {
#pragma unroll
                for (int i = 0; i < 2; i++) {
                    wmma::load_matrix_sync(af[i], &Ss[(wm * 32 + i * 16) * FST + kc], FST);
                    frag_to_tf32(af[i]);
                }
#pragma unroll
                for (int j = 0; j < 2; j++) {
                    wmma::load_matrix_sync(bf[j], &Vs[kc * FST + wn * 32 + j * 16], FST);
                    frag_to_tf32(bf[j]);
                }
#pragma unroll
                for (int i = 0; i < 2; i++)
#pragma unroll
                    for (int j = 0; j < 2; j++)
                        wmma::mma_sync(uf[i][j], af[i], bf[j], uf[i][j]);
            }
            __syncthreads();   // everyone done reading Ss as A operand
#pragma unroll
            for (int i = 0; i < 2; i++)
#pragma unroll
                for (int j = 0; j < 2; j++)
                    wmma::store_matrix_sync(&Ss[(wm * 32 + i * 16) * FST + wn * 32 + j * 16],
                                            uf[i][j], FST, wmma::mem_row_major);
        }
        __syncthreads();

        // O = O*alpha(row) + U
#pragma unroll
        for (int i = 0; i < 32; i++) {
            int idx = tid + i * 256;
            int r = idx >> 6, c = idx & 63;
            Os[r * FST + c] = Os[r * FST + c] * aS[r] + Ss[r * FST + c];
        }
        __syncthreads();
    }

    // epilogue: normalize and write out
    float* Og = Oout + ((size_t)(b * SEQ + mt * FBM)) * DMODEL + h * DKHEAD;
#pragma unroll
    for (int i = 0; i < 32; i++) {
        int idx = tid + i * 256;
        int r = idx >> 6, c = idx & 63;
        Og[(size_t)r * DMODEL + c] = Os[r * FST + c] / lS[r];
    }
}

// ---------------- elementwise ----------------
__global__ void bias_act_kernel(float* __restrict__ y, const float* __restrict__ bias,
                                int nmask, long long total, int relu) {
    long long i = (long long)blockIdx.x * blockDim.x + threadIdx.x;
    long long stride = (long long)gridDim.x * blockDim.x;
    for (; i < total; i += stride) {
        float v = y[i] + bias[(int)(i & nmask)];
        y[i] = relu ? fmaxf(v, 0.f) : v;
    }
}

__global__ void ln_kernel(const float* __restrict__ a, const float* __restrict__ bsrc,
                          const float* __restrict__ bias,
                          const float* __restrict__ gamma, const float* __restrict__ beta,
                          float* __restrict__ out) {
    int row = blockIdx.x;
    const float* ar = a + (size_t)row * DMODEL;
    const float* br = bsrc + (size_t)row * DMODEL;
    float v[4];
    float s = 0.f;
#pragma unroll
    for (int i = 0; i < 4; i++) {
        int c = threadIdx.x + i * 256;
        v[i] = ar[c] + br[c] + bias[c];
        s += v[i];
    }
    s = blockSum256(s);
    float mu = s * (1.0f / DMODEL);
    float q = 0.f;
#pragma unroll
    for (int i = 0; i < 4; i++) { float d = v[i] - mu; q += d * d; }
    q = blockSum256(q);
    float rstd = rsqrtf(q * (1.0f / DMODEL) + 1e-5f);
#pragma unroll
    for (int i = 0; i < 4; i++) {
        int c = threadIdx.x + i * 256;
        out[(size_t)row * DMODEL + c] = (v[i] - mu) * rstd * gamma[c] + beta[c];
    }
}

// ---------------- launch ----------------
extern "C" void kernel_launch(void* const* d_in, const int* in_sizes, int n_in,
                              void* d_out, int out_size) {
    const float* x    = (const float*)d_in[0];
    const int*   mask = (const int*)  d_in[1];
    const float* Wq   = (const float*)d_in[2];
    const float* bq   = (const float*)d_in[3];
    const float* Wk   = (const float*)d_in[4];
    const float* bk   = (const float*)d_in[5];
    const float* Wv   = (const float*)d_in[6];
    const float* bv   = (const float*)d_in[7];
    const float* Wo   = (const float*)d_in[8];
    const float* bo   = (const float*)d_in[9];
    const float* W1   = (const float*)d_in[10];
    const float* b1   = (const float*)d_in[11];
    const float* W2   = (const float*)d_in[12];
    const float* b2   = (const float*)d_in[13];
    const float* g1   = (const float*)d_in[14];
    const float* be1  = (const float*)d_in[15];
    const float* g2   = (const float*)d_in[16];
    const float* be2  = (const float*)d_in[17];
    float* out = (float*)d_out;

    float *Q, *Kb, *V, *At, *Ao, *H, *F1, *F2;
    cudaGetSymbolAddress((void**)&Q,  g_Q);
    cudaGetSymbolAddress((void**)&Kb, g_Kb);
    cudaGetSymbolAddress((void**)&V,  g_V);
    cudaGetSymbolAddress((void**)&At, g_attn);
    cudaGetSymbolAddress((void**)&Ao, g_attnout);
    cudaGetSymbolAddress((void**)&H,  g_h);
    cudaGetSymbolAddress((void**)&F1, g_ffmid);
    cudaGetSymbolAddress((void**)&F2, g_ffout);

    cudaFuncSetAttribute(gemm_nn, cudaFuncAttributeMaxDynamicSharedMemorySize, GEMM_SMEM_BYTES);
    cudaFuncSetAttribute(flash_kernel, cudaFuncAttributeMaxDynamicSharedMemorySize, FLASH_SMEM_BYTES);

    const dim3 thr(256);

    // QKV projections (bias folded into flash)
    dim3 gproj(DMODEL / BN, MROWS / BM);
    gemm_nn<<<gproj, thr, GEMM_SMEM_BYTES>>>(x, Wq, Q,  MROWS, DMODEL, DMODEL, DMODEL, DMODEL, DMODEL);
    gemm_nn<<<gproj, thr, GEMM_SMEM_BYTES>>>(x, Wk, Kb, MROWS, DMODEL, DMODEL, DMODEL, DMODEL, DMODEL);
    gemm_nn<<<gproj, thr, GEMM_SMEM_BYTES>>>(x, Wv, V,  MROWS, DMODEL, DMODEL, DMODEL, DMODEL, DMODEL);

    // fused attention -> At
    {
        dim3 g(SEQ / FBM, BATCH * NHEADS);
        flash_kernel<<<g, thr, FLASH_SMEM_BYTES>>>(Q, Kb, V, bq, bk, bv, mask, At);
    }

    // attn_out = At @ Wo (bo folded into LN1)
    gemm_nn<<<gproj, thr, GEMM_SMEM_BYTES>>>(At, Wo, Ao, MROWS, DMODEL, DMODEL, DMODEL, DMODEL, DMODEL);

    // h = LN(x + Ao + bo)
    ln_kernel<<<MROWS, thr>>>(x, Ao, bo, g1, be1, H);

    // ff_mid = relu(h @ W1 + b1)
    {
        dim3 g(DFF / BN, MROWS / BM);
        gemm_nn<<<g, thr, GEMM_SMEM_BYTES>>>(H, W1, F1, MROWS, DFF, DMODEL, DMODEL, DFF, DFF);
        bias_act_kernel<<<4096, thr>>>(F1, b1, DFF - 1, (long long)MROWS * DFF, 1);
    }

    // ff_out = F1 @ W2 (b2 folded into LN2)
    gemm_nn<<<gproj, thr, GEMM_SMEM_BYTES>>>(F1, W2, F2, MROWS, DMODEL, DFF, DFF, DMODEL, DMODEL);

    // out = LN(h + F2 + b2)
    ln_kernel<<<MROWS, thr>>>(H, F2, b2, g2, be2, out);
}

// round 7
// speedup vs baseline: 1.5125x; 1.4898x over previous
#include <cuda_runtime.h>
#include <cuda_bf16.h>
#include <mma.h>
#include <cstdint>

using namespace nvcuda;

#define DMODEL 1024
#define NHEADS 16
#define DKHEAD 64
#define DFF    4096
#define BATCH  2
#define SEQ    2048
#define MROWS  (BATCH*SEQ)   // 4096

// ---------------- scratch ----------------
__device__ float g_Q[(size_t)MROWS*DMODEL];
__device__ float g_Kb[(size_t)MROWS*DMODEL];
__device__ float g_V[(size_t)MROWS*DMODEL];
__device__ float g_attn[(size_t)MROWS*DMODEL];
__device__ float g_attnout[(size_t)MROWS*DMODEL];
__device__ float g_h[(size_t)MROWS*DMODEL];
__device__ float g_ffmid[(size_t)MROWS*DFF];
__device__ float g_ffout[(size_t)MROWS*DMODEL];

// ---------------- helpers ----------------
template<class Frag>
__device__ __forceinline__ void frag_to_tf32(Frag& f) {
#pragma unroll
    for (int t = 0; t < f.num_elements; t++) f.x[t] = wmma::__float_to_tf32(f.x[t]);
}

__device__ __forceinline__ uint32_t f2tf(float x) {
    uint32_t r;
    asm("cvt.rna.tf32.f32 %0, %1;" : "=r"(r) : "f"(x));
    return r;
}

__device__ __forceinline__ void mma_tf32(float* c, const uint32_t* a, const uint32_t* b) {
    asm volatile(
        "mma.sync.aligned.m16n8k8.row.col.f32.tf32.tf32.f32 "
        "{%0,%1,%2,%3}, {%4,%5,%6,%7}, {%8,%9}, {%0,%1,%2,%3};"
        : "+f"(c[0]), "+f"(c[1]), "+f"(c[2]), "+f"(c[3])
        : "r"(a[0]), "r"(a[1]), "r"(a[2]), "r"(a[3]), "r"(b[0]), "r"(b[1]));
}

__device__ __forceinline__ void cp16(float* s, const float* g) {
    uint32_t sa = (uint32_t)__cvta_generic_to_shared(s);
    asm volatile("cp.async.cg.shared.global [%0], [%1], 16;" :: "r"(sa), "l"(g));
}
__device__ __forceinline__ void cp_commit() { asm volatile("cp.async.commit_group;"); }

__device__ __forceinline__ float warpSum(float v) {
#pragma unroll
    for (int o = 16; o; o >>= 1) v += __shfl_xor_sync(0xffffffffu, v, o);
    return v;
}
__device__ float blockSum256(float v) {
    __shared__ float s[8];
    v = warpSum(v);
    if ((threadIdx.x & 31) == 0) s[threadIdx.x >> 5] = v;
    __syncthreads();
    if (threadIdx.x < 32) {
        float w = (threadIdx.x < 8) ? s[threadIdx.x] : 0.f;
        w = warpSum(w);
        if (threadIdx.x == 0) s[0] = w;
    }
    __syncthreads();
    float r = s[0];
    __syncthreads();
    return r;
}

// ---------------- cp.async double-buffered TF32 NN GEMM ----------------
constexpr int BM = 128, BN = 128, BK = 32;
constexpr int AS_STRIDE = BK + 4;            // 36
constexpr int BS_STRIDE = BN + 4;            // 132
constexpr int AS_STAGE = BM * AS_STRIDE;     // 4608
constexpr int BS_STAGE = BK * BS_STRIDE;     // 4224
constexpr int GEMM_SMEM_BYTES = (2 * AS_STAGE + 2 * BS_STAGE) * 4;  // 70656

__global__ void __launch_bounds__(256, 2) gemm_nn(
    const float* __restrict__ A, const float* __restrict__ B, float* __restrict__ C,
    int M, int N, int K, int lda, int ldb, int ldc)
{
    extern __shared__ float sm[];
    float* As = sm;
    float* Bs = sm + 2 * AS_STAGE;

    const int m0 = blockIdx.y * BM;
    const int n0 = blockIdx.x * BN;
    const int tid = threadIdx.x;
    const int warp = tid >> 5;
    const int wm = warp >> 1;
    const int wn = warp & 1;

    wmma::fragment<wmma::matrix_a, 16, 16, 8, wmma::precision::tf32, wmma::row_major> af[2];
    wmma::fragment<wmma::matrix_b, 16, 16, 8, wmma::precision::tf32, wmma::row_major> bf[4];
    wmma::fragment<wmma::accumulator, 16, 16, 8, float> cf[2][4];
#pragma unroll
    for (int i = 0; i < 2; i++)
#pragma unroll
        for (int j = 0; j < 4; j++) wmma::fill_fragment(cf[i][j], 0.0f);

    auto loadA = [&](int st, int kk) {
#pragma unroll
        for (int i = 0; i < 4; i++) {
            int idx = tid + i * 256;
            int r = idx >> 3, c4 = (idx & 7) * 4;
            cp16(&As[st * AS_STAGE + r * AS_STRIDE + c4],
                 &A[(size_t)(m0 + r) * lda + kk + c4]);
        }
    };
    auto loadB = [&](int st, int kk) {
#pragma unroll
        for (int i = 0; i < 4; i++) {
            int idx = tid + i * 256;
            int r = idx >> 5, c4 = (idx & 31) * 4;
            cp16(&Bs[st * BS_STAGE + r * BS_STRIDE + c4],
                 &B[(size_t)(kk + r) * ldb + n0 + c4]);
        }
    };

    loadA(0, 0); loadB(0, 0); cp_commit();

    const int nk = K / BK;
    for (int t = 0; t < nk; t++) {
        if (t + 1 < nk) {
            loadA((t + 1) & 1, (t + 1) * BK);
            loadB((t + 1) & 1, (t + 1) * BK);
            cp_commit();
            asm volatile("cp.async.wait_group 1;");
        } else {
            asm volatile("cp.async.wait_group 0;");
        }
        __syncthreads();

        const int st = t & 1;
        const float* Ab = &As[st * AS_STAGE];
        const float* Bb = &Bs[st * BS_STAGE];
#pragma unroll
        for (int k4 = 0; k4 < 4; k4++) {
            const int kc = k4 * 8;
#pragma unroll
            for (int i = 0; i < 2; i++) {
                wmma::load_matrix_sync(af[i], &Ab[(wm * 32 + i * 16) * AS_STRIDE + kc], AS_STRIDE);
                frag_to_tf32(af[i]);
            }
#pragma unroll
            for (int j = 0; j < 4; j++) {
                wmma::load_matrix_sync(bf[j], &Bb[kc * BS_STRIDE + wn * 64 + j * 16], BS_STRIDE);
                frag_to_tf32(bf[j]);
            }
#pragma unroll
            for (int i = 0; i < 2; i++)
#pragma unroll
                for (int j = 0; j < 4; j++)
                    wmma::mma_sync(cf[i][j], af[i], bf[j], cf[i][j]);
        }
        __syncthreads();
    }

#pragma unroll
    for (int i = 0; i < 2; i++)
#pragma unroll
        for (int j = 0; j < 4; j++)
            wmma::store_matrix_sync(&C[(size_t)(m0 + wm * 32 + i * 16) * ldc + n0 + wn * 64 + j * 16],
                                    cf[i][j], ldc, wmma::mem_row_major);
}

// ---------------- flash attention v2: raw mma, register-resident O ----------------
// grid (SEQ/128, BATCH*NHEADS), 256 threads (8 warps, 16 Q-rows each).
// Q in A-fragments (regs), O and S in accumulator regs; P via warp-private smem.
constexpr int FBM = 128, FBN = 64;
constexpr int KVST = 72;   // 64 + 8: stride makes B-frag smem reads conflict-free
constexpr int PST  = 72;
// smem: Ks[64*72] u32, Vs[64*72] u32, Ps[8 warps][16*72] u32, mk[64] int
constexpr int FLASH_SMEM_BYTES = (64 * KVST + 64 * KVST + 8 * 16 * PST + 64) * 4;  // 73984

__global__ void __launch_bounds__(256) flash_kernel(
    const float* __restrict__ Q, const float* __restrict__ K, const float* __restrict__ V,
    const float* __restrict__ bq, const float* __restrict__ bk, const float* __restrict__ bv,
    const int* __restrict__ mask, float* __restrict__ Oout)
{
    extern __shared__ uint32_t usm[];
    uint32_t* Ks = usm;
    uint32_t* Vs = Ks + 64 * KVST;
    uint32_t* Psb = Vs + 64 * KVST;
    int* mkS = (int*)(Psb + 8 * 16 * PST);

    const int mt = blockIdx.x;
    const int bh = blockIdx.y;
    const int b = bh >> 4, h = bh & 15;
    const int tid = threadIdx.x, warp = tid >> 5, lane = tid & 31;
    const int g = lane >> 2, q = lane & 3;

    uint32_t* Ps = Psb + warp * 16 * PST;

    const float* Kg = K + ((size_t)(b * SEQ)) * DMODEL + h * DKHEAD;
    const float* Vg = V + ((size_t)(b * SEQ)) * DMODEL + h * DKHEAD;

    // Q rows owned by this thread: r0 = g, r1 = g+8 within warp's 16-row tile
    const size_t qrow0 = (size_t)(b * SEQ + mt * FBM + warp * 16 + g) * DMODEL + h * DKHEAD;
    const float* Q0 = Q + qrow0;
    const float* Q1 = Q0 + 8 * DMODEL;
    const float* bqh = bq + h * DKHEAD;
    const float* bkh = bk + h * DKHEAD;
    const float* bvh = bv + h * DKHEAD;

    // Q A-fragments (scaled by 1/sqrt(dk)), loaded once
    uint32_t qa[8][4];
#pragma unroll
    for (int kt = 0; kt < 8; kt++) {
        int c0 = kt * 8 + q, c1 = c0 + 4;
        qa[kt][0] = f2tf((Q0[c0] + bqh[c0]) * 0.125f);
        qa[kt][1] = f2tf((Q1[c0] + bqh[c0]) * 0.125f);
        qa[kt][2] = f2tf((Q0[c1] + bqh[c1]) * 0.125f);
        qa[kt][3] = f2tf((Q1[c1] + bqh[c1]) * 0.125f);
    }

    float o[8][4];
#pragma unroll
    for (int n = 0; n < 8; n++)
#pragma unroll
        for (int c = 0; c < 4; c++) o[n][c] = 0.f;
    float m0 = -1e30f, m1 = -1e30f, l0 = 0.f, l1 = 0.f;

    for (int j0 = 0; j0 < SEQ; j0 += FBN) {
        // load K,V tile 64x64 -> smem as tf32 (bias folded); 4 float4 each per thread
#pragma unroll
        for (int i = 0; i < 4; i++) {
            int idx = tid + i * 256;
            int r = idx >> 4, c4 = (idx & 15) * 4;
            float4 kv = *(const float4*)&Kg[(size_t)(j0 + r) * DMODEL + c4];
            uint4 kk;
            kk.x = f2tf(kv.x + bkh[c4 + 0]); kk.y = f2tf(kv.y + bkh[c4 + 1]);
            kk.z = f2tf(kv.z + bkh[c4 + 2]); kk.w = f2tf(kv.w + bkh[c4 + 3]);
            *(uint4*)&Ks[r * KVST + c4] = kk;
            float4 vv = *(const float4*)&Vg[(size_t)(j0 + r) * DMODEL + c4];
            uint4 vu;
            vu.x = f2tf(vv.x + bvh[c4 + 0]); vu.y = f2tf(vv.y + bvh[c4 + 1]);
            vu.z = f2tf(vv.z + bvh[c4 + 2]); vu.w = f2tf(vv.w + bvh[c4 + 3]);
            *(uint4*)&Vs[r * KVST + c4] = vu;
        }
        if (tid < 64) mkS[tid] = mask[(size_t)b * SEQ + j0 + tid];
        __syncthreads();

        // S = Q @ K^T : 8 n-tiles of m16n8
        float s[8][4];
#pragma unroll
        for (int n = 0; n < 8; n++) {
            s[n][0] = s[n][1] = s[n][2] = s[n][3] = 0.f;
#pragma unroll
            for (int kt = 0; kt < 8; kt++) {
                uint32_t bfr[2];
                bfr[0] = Ks[(n * 8 + g) * KVST + kt * 8 + q];
                bfr[1] = Ks[(n * 8 + g) * KVST + kt * 8 + q + 4];
                mma_tf32(s[n], qa[kt], bfr);
            }
        }

        // mask + online softmax (rows r0, r1 per lane; quad shuffle reduces)
        float rm0 = -1e30f, rm1 = -1e30f;
#pragma unroll
        for (int n = 0; n < 8; n++) {
            int col = n * 8 + 2 * q;
            if (mkS[col] == 0)     { s[n][0] = -1e30f; s[n][2] = -1e30f; }
            if (mkS[col + 1] == 0) { s[n][1] = -1e30f; s[n][3] = -1e30f; }
            rm0 = fmaxf(rm0, fmaxf(s[n][0], s[n][1]));
            rm1 = fmaxf(rm1, fmaxf(s[n][2], s[n][3]));
        }
        rm0 = fmaxf(rm0, __shfl_xor_sync(0xffffffffu, rm0, 1));
        rm0 = fmaxf(rm0, __shfl_xor_sync(0xffffffffu, rm0, 2));
        rm1 = fmaxf(rm1, __shfl_xor_sync(0xffffffffu, rm1, 1));
        rm1 = fmaxf(rm1, __shfl_xor_sync(0xffffffffu, rm1, 2));

        float mn0 = fmaxf(m0, rm0), mn1 = fmaxf(m1, rm1);
        float al0 = __expf(m0 - mn0), al1 = __expf(m1 - mn1);
        m0 = mn0; m1 = mn1;

        float sum0 = 0.f, sum1 = 0.f;
#pragma unroll
        for (int n = 0; n < 8; n++) {
            s[n][0] = __expf(s[n][0] - m0);
            s[n][1] = __expf(s[n][1] - m0);
            s[n][2] = __expf(s[n][2] - m1);
            s[n][3] = __expf(s[n][3] - m1);
            sum0 += s[n][0] + s[n][1];
            sum1 += s[n][2] + s[n][3];
            // store P (tf32) to warp-private buffer, C-layout
            uint2 p0; p0.x = f2tf(s[n][0]); p0.y = f2tf(s[n][1]);
            *(uint2*)&Ps[g * PST + n * 8 + 2 * q] = p0;
            uint2 p1; p1.x = f2tf(s[n][2]); p1.y = f2tf(s[n][3]);
            *(uint2*)&Ps[(g + 8) * PST + n * 8 + 2 * q] = p1;
        }
        sum0 += __shfl_xor_sync(0xffffffffu, sum0, 1);
        sum0 += __shfl_xor_sync(0xffffffffu, sum0, 2);
        sum1 += __shfl_xor_sync(0xffffffffu, sum1, 1);
        sum1 += __shfl_xor_sync(0xffffffffu, sum1, 2);
        l0 = l0 * al0 + sum0;
        l1 = l1 * al1 + sum1;

#pragma unroll
        for (int n = 0; n < 8; n++) {
            o[n][0] *= al0; o[n][1] *= al0;
            o[n][2] *= al1; o[n][3] *= al1;
        }
        __syncwarp();

        // O += P @ V : n = dk tile, kt = j tile
#pragma unroll
        for (int kt = 0; kt < 8; kt++) {
            uint32_t pa[4];
            pa[0] = Ps[g * PST + kt * 8 + q];
            pa[1] = Ps[(g + 8) * PST + kt * 8 + q];
            pa[2] = Ps[g * PST + kt * 8 + q + 4];
            pa[3] = Ps[(g + 8) * PST + kt * 8 + q + 4];
#pragma unroll
            for (int n = 0; n < 8; n++) {
                uint32_t bfr[2];
                bfr[0] = Vs[(kt * 8 + q) * KVST + n * 8 + g];
                bfr[1] = Vs[(kt * 8 + q + 4) * KVST + n * 8 + g];
                mma_tf32(o[n], pa, bfr);
            }
        }
        __syncthreads();
    }

    // epilogue: normalize, write
    float inv0 = 1.f / l0, inv1 = 1.f / l1;
    float* Og = Oout + qrow0;
    float* Og1 = Og + 8 * DMODEL;
#pragma unroll
    for (int n = 0; n < 8; n++) {
        float2 v0 = make_float2(o[n][0] * inv0, o[n][1] * inv0);
        *(float2*)&Og[n * 8 + 2 * q] = v0;
        float2 v1 = make_float2(o[n][2] * inv1, o[n][3] * inv1);
        *(float2*)&Og1[n * 8 + 2 * q] = v1;
    }
}

// ---------------- elementwise ----------------
__global__ void bias_act_kernel(float* __restrict__ y, const float* __restrict__ bias,
                                int nmask, long long total, int relu) {
    long long i = (long long)blockIdx.x * blockDim.x + threadIdx.x;
    long long stride = (long long)gridDim.x * blockDim.x;
    for (; i < total; i += stride) {
        float v = y[i] + bias[(int)(i & nmask)];
        y[i] = relu ? fmaxf(v, 0.f) : v;
    }
}

__global__ void ln_kernel(const float* __restrict__ a, const float* __restrict__ bsrc,
                          const float* __restrict__ bias,
                          const float* __restrict__ gamma, const float* __restrict__ beta,
                          float* __restrict__ out) {
    int row = blockIdx.x;
    const float* ar = a + (size_t)row * DMODEL;
    const float* br = bsrc + (size_t)row * DMODEL;
    float v[4];
    float s = 0.f;
#pragma unroll
    for (int i = 0; i < 4; i++) {
        int c = threadIdx.x + i * 256;
        v[i] = ar[c] + br[c] + bias[c];
        s += v[i];
    }
    s = blockSum256(s);
    float mu = s * (1.0f / DMODEL);
    float qv = 0.f;
#pragma unroll
    for (int i = 0; i < 4; i++) { float d = v[i] - mu; qv += d * d; }
    qv = blockSum256(qv);
    float rstd = rsqrtf(qv * (1.0f / DMODEL) + 1e-5f);
#pragma unroll
    for (int i = 0; i < 4; i++) {
        int c = threadIdx.x + i * 256;
        out[(size_t)row * DMODEL + c] = (v[i] - mu) * rstd * gamma[c] + beta[c];
    }
}

// ---------------- launch ----------------
extern "C" void kernel_launch(void* const* d_in, const int* in_sizes, int n_in,
                              void* d_out, int out_size) {
    const float* x    = (const float*)d_in[0];
    const int*   mask = (const int*)  d_in[1];
    const float* Wq   = (const float*)d_in[2];
    const float* bq   = (const float*)d_in[3];
    const float* Wk   = (const float*)d_in[4];
    const float* bk   = (const float*)d_in[5];
    const float* Wv   = (const float*)d_in[6];
    const float* bv   = (const float*)d_in[7];
    const float* Wo   = (const float*)d_in[8];
    const float* bo   = (const float*)d_in[9];
    const float* W1   = (const float*)d_in[10];
    const float* b1   = (const float*)d_in[11];
    const float* W2   = (const float*)d_in[12];
    const float* b2   = (const float*)d_in[13];
    const float* g1   = (const float*)d_in[14];
    const float* be1  = (const float*)d_in[15];
    const float* g2   = (const float*)d_in[16];
    const float* be2  = (const float*)d_in[17];
    float* out = (float*)d_out;

    float *Q, *Kb, *V, *At, *Ao, *H, *F1, *F2;
    cudaGetSymbolAddress((void**)&Q,  g_Q);
    cudaGetSymbolAddress((void**)&Kb, g_Kb);
    cudaGetSymbolAddress((void**)&V,  g_V);
    cudaGetSymbolAddress((void**)&At, g_attn);
    cudaGetSymbolAddress((void**)&Ao, g_attnout);
    cudaGetSymbolAddress((void**)&H,  g_h);
    cudaGetSymbolAddress((void**)&F1, g_ffmid);
    cudaGetSymbolAddress((void**)&F2, g_ffout);

    cudaFuncSetAttribute(gemm_nn, cudaFuncAttributeMaxDynamicSharedMemorySize, GEMM_SMEM_BYTES);
    cudaFuncSetAttribute(flash_kernel, cudaFuncAttributeMaxDynamicSharedMemorySize, FLASH_SMEM_BYTES);

    const dim3 thr(256);

    // QKV projections (biases folded into flash)
    dim3 gproj(DMODEL / BN, MROWS / BM);
    gemm_nn<<<gproj, thr, GEMM_SMEM_BYTES>>>(x, Wq, Q,  MROWS, DMODEL, DMODEL, DMODEL, DMODEL, DMODEL);
    gemm_nn<<<gproj, thr, GEMM_SMEM_BYTES>>>(x, Wk, Kb, MROWS, DMODEL, DMODEL, DMODEL, DMODEL, DMODEL);
    gemm_nn<<<gproj, thr, GEMM_SMEM_BYTES>>>(x, Wv, V,  MROWS, DMODEL, DMODEL, DMODEL, DMODEL, DMODEL);

    // fused attention -> At
    {
        dim3 g(SEQ / FBM, BATCH * NHEADS);
        flash_kernel<<<g, thr, FLASH_SMEM_BYTES>>>(Q, Kb, V, bq, bk, bv, mask, At);
    }

    // attn_out = At @ Wo (bo folded into LN1)
    gemm_nn<<<gproj, thr, GEMM_SMEM_BYTES>>>(At, Wo, Ao, MROWS, DMODEL, DMODEL, DMODEL, DMODEL, DMODEL);

    // h = LN(x + Ao + bo)
    ln_kernel<<<MROWS, thr>>>(x, Ao, bo, g1, be1, H);

    // ff_mid = relu(h @ W1 + b1)
    {
        dim3 g(DFF / BN, MROWS / BM);
        gemm_nn<<<g, thr, GEMM_SMEM_BYTES>>>(H, W1, F1, MROWS, DFF, DMODEL, DMODEL, DFF, DFF);
        bias_act_kernel<<<4096, thr>>>(F1, b1, DFF - 1, (long long)MROWS * DFF, 1);
    }

    // ff_out = F1 @ W2 (b2 folded into LN2)
    gemm_nn<<<gproj, thr, GEMM_SMEM_BYTES>>>(F1, W2, F2, MROWS, DMODEL, DFF, DFF, DMODEL, DMODEL);

    // out = LN(h + F2 + b2)
    ln_kernel<<<MROWS, thr>>>(H, F2, b2, g2, be2, out);
}

// round 9
// speedup vs baseline: 1.6254x; 1.0746x over previous
#include <cuda_runtime.h>
#include <cuda_bf16.h>
#include <mma.h>
#include <cstdint>

using namespace nvcuda;

#define DMODEL 1024
#define NHEADS 16
#define DKHEAD 64
#define DFF    4096
#define BATCH  2
#define SEQ    2048
#define MROWS  (BATCH*SEQ)   // 4096

// ---------------- scratch ----------------
__device__ float g_Q[(size_t)MROWS*DMODEL];
__device__ float g_Kb[(size_t)MROWS*DMODEL];
__device__ float g_V[(size_t)MROWS*DMODEL];
__device__ float g_attn[(size_t)MROWS*DMODEL];
__device__ float g_attnout[(size_t)MROWS*DMODEL];
__device__ float g_h[(size_t)MROWS*DMODEL];
__device__ float g_ffmid[(size_t)MROWS*DFF];
__device__ float g_ffout[(size_t)MROWS*DMODEL];

// ---------------- helpers ----------------
__device__ __forceinline__ uint32_t f2tf(float x) {
    uint32_t r;
    asm("cvt.rna.tf32.f32 %0, %1;" : "=r"(r) : "f"(x));
    return r;
}

__device__ __forceinline__ void mma_tf32(float* c, const uint32_t* a, const uint32_t* b) {
    asm volatile(
        "mma.sync.aligned.m16n8k8.row.col.f32.tf32.tf32.f32 "
        "{%0,%1,%2,%3}, {%4,%5,%6,%7}, {%8,%9}, {%0,%1,%2,%3};"
        : "+f"(c[0]), "+f"(c[1]), "+f"(c[2]), "+f"(c[3])
        : "r"(a[0]), "r"(a[1]), "r"(a[2]), "r"(a[3]), "r"(b[0]), "r"(b[1]));
}

__device__ __forceinline__ void cp16(void* s, const void* g) {
    uint32_t sa = (uint32_t)__cvta_generic_to_shared(s);
    asm volatile("cp.async.cg.shared.global [%0], [%1], 16;" :: "r"(sa), "l"(g));
}
__device__ __forceinline__ void cp_commit() { asm volatile("cp.async.commit_group;"); }

__device__ __forceinline__ float warpSum(float v) {
#pragma unroll
    for (int o = 16; o; o >>= 1) v += __shfl_xor_sync(0xffffffffu, v, o);
    return v;
}
__device__ float blockSum256(float v) {
    __shared__ float s[8];
    v = warpSum(v);
    if ((threadIdx.x & 31) == 0) s[threadIdx.x >> 5] = v;
    __syncthreads();
    if (threadIdx.x < 32) {
        float w = (threadIdx.x < 8) ? s[threadIdx.x] : 0.f;
        w = warpSum(w);
        if (threadIdx.x == 0) s[0] = w;
    }
    __syncthreads();
    float r = s[0];
    __syncthreads();
    return r;
}

// ---------------- cp.async double-buffered TF32 NN GEMM (no RN-convert: HW truncates) ----------------
constexpr int BM = 128, BN = 128, BK = 32;
constexpr int AS_STRIDE = BK + 4;            // 36
constexpr int BS_STRIDE = BN + 4;            // 132
constexpr int AS_STAGE = BM * AS_STRIDE;     // 4608
constexpr int BS_STAGE = BK * BS_STRIDE;     // 4224
constexpr int GEMM_SMEM_BYTES = (2 * AS_STAGE + 2 * BS_STAGE) * 4;  // 70656

__global__ void __launch_bounds__(256, 2) gemm_nn(
    const float* __restrict__ A, const float* __restrict__ B, float* __restrict__ C,
    int M, int N, int K, int lda, int ldb, int ldc)
{
    extern __shared__ float sm[];
    float* As = sm;
    float* Bs = sm + 2 * AS_STAGE;

    const int m0 = blockIdx.y * BM;
    const int n0 = blockIdx.x * BN;
    const int tid = threadIdx.x;
    const int warp = tid >> 5;
    const int wm = warp >> 1;
    const int wn = warp & 1;

    wmma::fragment<wmma::matrix_a, 16, 16, 8, wmma::precision::tf32, wmma::row_major> af[2];
    wmma::fragment<wmma::matrix_b, 16, 16, 8, wmma::precision::tf32, wmma::row_major> bf[4];
    wmma::fragment<wmma::accumulator, 16, 16, 8, float> cf[2][4];
#pragma unroll
    for (int i = 0; i < 2; i++)
#pragma unroll
        for (int j = 0; j < 4; j++) wmma::fill_fragment(cf[i][j], 0.0f);

    auto loadA = [&](int st, int kk) {
#pragma unroll
        for (int i = 0; i < 4; i++) {
            int idx = tid + i * 256;
            int r = idx >> 3, c4 = (idx & 7) * 4;
            cp16(&As[st * AS_STAGE + r * AS_STRIDE + c4],
                 &A[(size_t)(m0 + r) * lda + kk + c4]);
        }
    };
    auto loadB = [&](int st, int kk) {
#pragma unroll
        for (int i = 0; i < 4; i++) {
            int idx = tid + i * 256;
            int r = idx >> 5, c4 = (idx & 31) * 4;
            cp16(&Bs[st * BS_STAGE + r * BS_STRIDE + c4],
                 &B[(size_t)(kk + r) * ldb + n0 + c4]);
        }
    };

    loadA(0, 0); loadB(0, 0); cp_commit();

    const int nk = K / BK;
    for (int t = 0; t < nk; t++) {
        if (t + 1 < nk) {
            loadA((t + 1) & 1, (t + 1) * BK);
            loadB((t + 1) & 1, (t + 1) * BK);
            cp_commit();
            asm volatile("cp.async.wait_group 1;");
        } else {
            asm volatile("cp.async.wait_group 0;");
        }
        __syncthreads();

        const int st = t & 1;
        const float* Ab = &As[st * AS_STAGE];
        const float* Bb = &Bs[st * BS_STAGE];
#pragma unroll
        for (int k4 = 0; k4 < 4; k4++) {
            const int kc = k4 * 8;
#pragma unroll
            for (int i = 0; i < 2; i++)
                wmma::load_matrix_sync(af[i], &Ab[(wm * 32 + i * 16) * AS_STRIDE + kc], AS_STRIDE);
#pragma unroll
            for (int j = 0; j < 4; j++)
                wmma::load_matrix_sync(bf[j], &Bb[kc * BS_STRIDE + wn * 64 + j * 16], BS_STRIDE);
#pragma unroll
            for (int i = 0; i < 2; i++)
#pragma unroll
                for (int j = 0; j < 4; j++)
                    wmma::mma_sync(cf[i][j], af[i], bf[j], cf[i][j]);
        }
        __syncthreads();
    }

#pragma unroll
    for (int i = 0; i < 2; i++)
#pragma unroll
        for (int j = 0; j < 4; j++)
            wmma::store_matrix_sync(&C[(size_t)(m0 + wm * 32 + i * 16) * ldc + n0 + wn * 64 + j * 16],
                                    cf[i][j], ldc, wmma::mem_row_major);
}

// ---------------- flash attention v3 ----------------
// cp.async double-buffered raw K/V (K-bias dropped: softmax-invariant; V-bias in epilogue).
// Q in A-frags (bias+scale folded, RN-converted once). O,S in accumulators.
constexpr int FBM = 128, FBN = 64;
constexpr int KVST = 72;
constexpr int PST  = 72;
constexpr int KV_STAGE = 64 * KVST;          // 4608 u32 per stage per array
// smem u32: K[2][4608], V[2][4608], Ps[8][16*72]=9216, mask[2048]
constexpr int FLASH_SMEM_BYTES = (2 * KV_STAGE + 2 * KV_STAGE + 8 * 16 * PST + 2048) * 4; // 118784

__global__ void __launch_bounds__(256) flash_kernel(
    const float* __restrict__ Q, const float* __restrict__ K, const float* __restrict__ V,
    const float* __restrict__ bq, const float* __restrict__ bv,
    const int* __restrict__ mask, float* __restrict__ Oout)
{
    extern __shared__ uint32_t usm[];
    uint32_t* Ks = usm;                      // 2 stages
    uint32_t* Vs = Ks + 2 * KV_STAGE;        // 2 stages
    uint32_t* Psb = Vs + 2 * KV_STAGE;
    int* mkAll = (int*)(Psb + 8 * 16 * PST);

    const int mt = blockIdx.x;
    const int bh = blockIdx.y;
    const int b = bh >> 4, h = bh & 15;
    const int tid = threadIdx.x, warp = tid >> 5, lane = tid & 31;
    const int g = lane >> 2, q = lane & 3;

    uint32_t* Ps = Psb + warp * 16 * PST;

    const float* Kg = K + ((size_t)(b * SEQ)) * DMODEL + h * DKHEAD;
    const float* Vg = V + ((size_t)(b * SEQ)) * DMODEL + h * DKHEAD;

    const size_t qrow0 = (size_t)(b * SEQ + mt * FBM + warp * 16 + g) * DMODEL + h * DKHEAD;
    const float* Q0 = Q + qrow0;
    const float* Q1 = Q0 + 8 * DMODEL;
    const float* bqh = bq + h * DKHEAD;
    const float* bvh = bv + h * DKHEAD;

    // mask row for this batch, loaded once
#pragma unroll
    for (int i = 0; i < 8; i++)
        mkAll[tid + i * 256] = mask[(size_t)b * SEQ + tid + i * 256];

    // Q fragments (bias + 1/sqrt(dk) folded, RN-convert once)
    uint32_t qa[8][4];
#pragma unroll
    for (int kt = 0; kt < 8; kt++) {
        int c0 = kt * 8 + q, c1 = c0 + 4;
        qa[kt][0] = f2tf((Q0[c0] + bqh[c0]) * 0.125f);
        qa[kt][1] = f2tf((Q1[c0] + bqh[c0]) * 0.125f);
        qa[kt][2] = f2tf((Q0[c1] + bqh[c1]) * 0.125f);
        qa[kt][3] = f2tf((Q1[c1] + bqh[c1]) * 0.125f);
    }

    auto loadKV = [&](int st, int j0) {
#pragma unroll
        for (int i = 0; i < 4; i++) {
            int idx = tid + i * 256;
            int r = idx >> 4, c4 = (idx & 15) * 4;
            cp16(&Ks[st * KV_STAGE + r * KVST + c4], &Kg[(size_t)(j0 + r) * DMODEL + c4]);
            cp16(&Vs[st * KV_STAGE + r * KVST + c4], &Vg[(size_t)(j0 + r) * DMODEL + c4]);
        }
    };

    float o[8][4];
#pragma unroll
    for (int n = 0; n < 8; n++)
#pragma unroll
        for (int c = 0; c < 4; c++) o[n][c] = 0.f;
    float m0 = -1e30f, m1 = -1e30f, l0 = 0.f, l1 = 0.f;

    loadKV(0, 0); cp_commit();

    constexpr int NT = SEQ / FBN;   // 32
    for (int t = 0; t < NT; t++) {
        if (t + 1 < NT) {
            loadKV((t + 1) & 1, (t + 1) * FBN);
            cp_commit();
            asm volatile("cp.async.wait_group 1;");
        } else {
            asm volatile("cp.async.wait_group 0;");
        }
        __syncthreads();

        const uint32_t* Kt = Ks + (t & 1) * KV_STAGE;
        const uint32_t* Vt = Vs + (t & 1) * KV_STAGE;
        const int j0 = t * FBN;

        // S = Q @ K^T
        float s[8][4];
#pragma unroll
        for (int n = 0; n < 8; n++) {
            s[n][0] = s[n][1] = s[n][2] = s[n][3] = 0.f;
#pragma unroll
            for (int kt = 0; kt < 8; kt++) {
                uint32_t bfr[2];
                bfr[0] = Kt[(n * 8 + g) * KVST + kt * 8 + q];
                bfr[1] = Kt[(n * 8 + g) * KVST + kt * 8 + q + 4];
                mma_tf32(s[n], qa[kt], bfr);
            }
        }

        // mask + online softmax
        float rm0 = -1e30f, rm1 = -1e30f;
#pragma unroll
        for (int n = 0; n < 8; n++) {
            int col = j0 + n * 8 + 2 * q;
            if (mkAll[col] == 0)     { s[n][0] = -1e30f; s[n][2] = -1e30f; }
            if (mkAll[col + 1] == 0) { s[n][1] = -1e30f; s[n][3] = -1e30f; }
            rm0 = fmaxf(rm0, fmaxf(s[n][0], s[n][1]));
            rm1 = fmaxf(rm1, fmaxf(s[n][2], s[n][3]));
        }
        rm0 = fmaxf(rm0, __shfl_xor_sync(0xffffffffu, rm0, 1));
        rm0 = fmaxf(rm0, __shfl_xor_sync(0xffffffffu, rm0, 2));
        rm1 = fmaxf(rm1, __shfl_xor_sync(0xffffffffu, rm1, 1));
        rm1 = fmaxf(rm1, __shfl_xor_sync(0xffffffffu, rm1, 2));

        float mn0 = fmaxf(m0, rm0), mn1 = fmaxf(m1, rm1);
        float al0 = __expf(m0 - mn0), al1 = __expf(m1 - mn1);
        m0 = mn0; m1 = mn1;

        float sum0 = 0.f, sum1 = 0.f;
#pragma unroll
        for (int n = 0; n < 8; n++) {
            s[n][0] = __expf(s[n][0] - m0);
            s[n][1] = __expf(s[n][1] - m0);
            s[n][2] = __expf(s[n][2] - m1);
            s[n][3] = __expf(s[n][3] - m1);
            sum0 += s[n][0] + s[n][1];
            sum1 += s[n][2] + s[n][3];
            uint2 p0; p0.x = __float_as_uint(s[n][0]); p0.y = __float_as_uint(s[n][1]);
            *(uint2*)&Ps[g * PST + n * 8 + 2 * q] = p0;
            uint2 p1; p1.x = __float_as_uint(s[n][2]); p1.y = __float_as_uint(s[n][3]);
            *(uint2*)&Ps[(g + 8) * PST + n * 8 + 2 * q] = p1;
        }
        sum0 += __shfl_xor_sync(0xffffffffu, sum0, 1);
        sum0 += __shfl_xor_sync(0xffffffffu, sum0, 2);
        sum1 += __shfl_xor_sync(0xffffffffu, sum1, 1);
        sum1 += __shfl_xor_sync(0xffffffffu, sum1, 2);
        l0 = l0 * al0 + sum0;
        l1 = l1 * al1 + sum1;

#pragma unroll
        for (int n = 0; n < 8; n++) {
            o[n][0] *= al0; o[n][1] *= al0;
            o[n][2] *= al1; o[n][3] *= al1;
        }
        __syncwarp();

        // O += P @ V
#pragma unroll
        for (int kt = 0; kt < 8; kt++) {
            uint32_t pa[4];
            pa[0] = Ps[g * PST + kt * 8 + q];
            pa[1] = Ps[(g + 8) * PST + kt * 8 + q];
            pa[2] = Ps[g * PST + kt * 8 + q + 4];
            pa[3] = Ps[(g + 8) * PST + kt * 8 + q + 4];
#pragma unroll
            for (int n = 0; n < 8; n++) {
                uint32_t bfr[2];
                bfr[0] = Vt[(kt * 8 + q) * KVST + n * 8 + g];
                bfr[1] = Vt[(kt * 8 + q + 4) * KVST + n * 8 + g];
                mma_tf32(o[n], pa, bfr);
            }
        }
        __syncthreads();
    }

    // epilogue: normalize, add V-bias, write
    float inv0 = 1.f / l0, inv1 = 1.f / l1;
    float* Og = Oout + qrow0;
    float* Og1 = Og + 8 * DMODEL;
#pragma unroll
    for (int n = 0; n < 8; n++) {
        int c = n * 8 + 2 * q;
        float2 v0 = make_float2(o[n][0] * inv0 + bvh[c], o[n][1] * inv0 + bvh[c + 1]);
        *(float2*)&Og[c] = v0;
        float2 v1 = make_float2(o[n][2] * inv1 + bvh[c], o[n][3] * inv1 + bvh[c + 1]);
        *(float2*)&Og1[c] = v1;
    }
}

// ---------------- elementwise ----------------
__global__ void bias_act_kernel(float* __restrict__ y, const float* __restrict__ bias,
                                int nmask, long long total, int relu) {
    long long i = (long long)blockIdx.x * blockDim.x + threadIdx.x;
    long long stride = (long long)gridDim.x * blockDim.x;
    for (; i < total; i += stride) {
        float v = y[i] + bias[(int)(i & nmask)];
        y[i] = relu ? fmaxf(v, 0.f) : v;
    }
}

__global__ void ln_kernel(const float* __restrict__ a, const float* __restrict__ bsrc,
                          const float* __restrict__ bias,
                          const float* __restrict__ gamma, const float* __restrict__ beta,
                          float* __restrict__ out) {
    int row = blockIdx.x;
    const float* ar = a + (size_t)row * DMODEL;
    const float* br = bsrc + (size_t)row * DMODEL;
    float v[4];
    float s = 0.f;
#pragma unroll
    for (int i = 0; i < 4; i++) {
        int c = threadIdx.x + i * 256;
        v[i] = ar[c] + br[c] + bias[c];
        s += v[i];
    }
    s = blockSum256(s);
    float mu = s * (1.0f / DMODEL);
    float qv = 0.f;
#pragma unroll
    for (int i = 0; i < 4; i++) { float d = v[i] - mu; qv += d * d; }
    qv = blockSum256(qv);
    float rstd = rsqrtf(qv * (1.0f / DMODEL) + 1e-5f);
#pragma unroll
    for (int i = 0; i < 4; i++) {
        int c = threadIdx.x + i * 256;
        out[(size_t)row * DMODEL + c] = (v[i] - mu) * rstd * gamma[c] + beta[c];
    }
}

// ---------------- launch ----------------
extern "C" void kernel_launch(void* const* d_in, const int* in_sizes, int n_in,
                              void* d_out, int out_size) {
    const float* x    = (const float*)d_in[0];
    const int*   mask = (const int*)  d_in[1];
    const float* Wq   = (const float*)d_in[2];
    const float* bq   = (const float*)d_in[3];
    const float* Wk   = (const float*)d_in[4];
    const float* bk   = (const float*)d_in[5];
    const float* Wv   = (const float*)d_in[6];
    const float* bv   = (const float*)d_in[7];
    const float* Wo   = (const float*)d_in[8];
    const float* bo   = (const float*)d_in[9];
    const float* W1   = (const float*)d_in[10];
    const float* b1   = (const float*)d_in[11];
    const float* W2   = (const float*)d_in[12];
    const float* b2   = (const float*)d_in[13];
    const float* g1   = (const float*)d_in[14];
    const float* be1  = (const float*)d_in[15];
    const float* g2   = (const float*)d_in[16];
    const float* be2  = (const float*)d_in[17];
    float* out = (float*)d_out;
    (void)bk;

    float *Q, *Kb, *V, *At, *Ao, *H, *F1, *F2;
    cudaGetSymbolAddress((void**)&Q,  g_Q);
    cudaGetSymbolAddress((void**)&Kb, g_Kb);
    cudaGetSymbolAddress((void**)&V,  g_V);
    cudaGetSymbolAddress((void**)&At, g_attn);
    cudaGetSymbolAddress((void**)&Ao, g_attnout);
    cudaGetSymbolAddress((void**)&H,  g_h);
    cudaGetSymbolAddress((void**)&F1, g_ffmid);
    cudaGetSymbolAddress((void**)&F2, g_ffout);

    cudaFuncSetAttribute(gemm_nn, cudaFuncAttributeMaxDynamicSharedMemorySize, GEMM_SMEM_BYTES);
    cudaFuncSetAttribute(flash_kernel, cudaFuncAttributeMaxDynamicSharedMemorySize, FLASH_SMEM_BYTES);

    const dim3 thr(256);

    dim3 gproj(DMODEL / BN, MROWS / BM);
    gemm_nn<<<gproj, thr, GEMM_SMEM_BYTES>>>(x, Wq, Q,  MROWS, DMODEL, DMODEL, DMODEL, DMODEL, DMODEL);
    gemm_nn<<<gproj, thr, GEMM_SMEM_BYTES>>>(x, Wk, Kb, MROWS, DMODEL, DMODEL, DMODEL, DMODEL, DMODEL);
    gemm_nn<<<gproj, thr, GEMM_SMEM_BYTES>>>(x, Wv, V,  MROWS, DMODEL, DMODEL, DMODEL, DMODEL, DMODEL);

    {
        dim3 g(SEQ / FBM, BATCH * NHEADS);
        flash_kernel<<<g, thr, FLASH_SMEM_BYTES>>>(Q, Kb, V, bq, bv, mask, At);
    }

    gemm_nn<<<gproj, thr, GEMM_SMEM_BYTES>>>(At, Wo, Ao, MROWS, DMODEL, DMODEL, DMODEL, DMODEL, DMODEL);
    ln_kernel<<<MROWS, thr>>>(x, Ao, bo, g1, be1, H);

    {
        dim3 g(DFF / BN, MROWS / BM);
        gemm_nn<<<g, thr, GEMM_SMEM_BYTES>>>(H, W1, F1, MROWS, DFF, DMODEL, DMODEL, DFF, DFF);
        bias_act_kernel<<<4096, thr>>>(F1, b1, DFF - 1, (long long)MROWS * DFF, 1);
    }

    gemm_nn<<<gproj, thr, GEMM_SMEM_BYTES>>>(F1, W2, F2, MROWS, DMODEL, DFF, DFF, DMODEL, DMODEL);
    ln_kernel<<<MROWS, thr>>>(H, F2, b2, g2, be2, out);
}